// round 5
// baseline (speedup 1.0000x reference)
#include <cuda_runtime.h>

#define LN 8      // layers
#define BN 64     // batch
#define TN 512    // time steps
#define HN 128    // hidden
#define ON 65     // output vocab
#define CPL 16    // CTAs per layer
#define UPC 8     // hidden units per CTA
#define GCOLS 32  // gate columns per CTA
#define NTHR 256
#define NCTA (LN * CPL)

// Inter-layer activation buffer, k-major: h of layer l at time t, [HN][BN].
__device__ float g_hbuf[LN][TN][HN][BN];
// Per-slice completion flags.
__device__ int g_flag[LN][TN][CPL];

__device__ __forceinline__ float sig_(float x) {
    return __fdividef(1.f, 1.f + __expf(-x));
}
__device__ __forceinline__ float th_(float x) {
    return 1.f - __fdividef(2.f, __expf(2.f * x) + 1.f);
}
__device__ __forceinline__ int ld_acq(const int* p) {
    int v; asm volatile("ld.global.acquire.gpu.b32 %0, [%1];" : "=r"(v) : "l"(p)); return v;
}
__device__ __forceinline__ void st_rel(int* p, int v) {
    asm volatile("st.global.release.gpu.b32 [%0], %1;" :: "l"(p), "r"(v));
}

__global__ void __launch_bounds__(256, 1) zero_flag_kernel() {
    int i = blockIdx.x * blockDim.x + threadIdx.x;
    if (i < LN * TN * CPL) (&g_flag[0][0][0])[i] = 0;
}

__global__ void __launch_bounds__(NTHR, 1) lstm_kernel(
    const int* __restrict__ x, const float* __restrict__ embed,
    const float* __restrict__ w_ih, const float* __restrict__ b_ih,
    const float* __restrict__ w_hh, const float* __restrict__ b_hh,
    float* __restrict__ out, int out_size)
{
    extern __shared__ float sm[];
    float* w_s  = sm;          // [2][128][32]: w_ih then w_hh slice, layout [k][lu*4+g]
    float* in_s = sm + 8192;   // [128][64] k-major input tile
    float* hp_s = sm + 16384;  // [128][64] k-major h_prev tile

    const int cta   = blockIdx.x;
    const int l     = cta >> 4;
    const int slice = cta & 15;
    const int tid   = threadIdx.x;
    const int warp  = tid >> 5;      // 0..7
    const int lane  = tid & 31;
    const int cg    = warp & 3;      // column group: cols cg*8 .. cg*8+7 (units cg*2, cg*2+1)
    const int row   = (warp >> 2) * 32 + lane;   // this thread's single batch row

    // ---- one-time: weight slice into SMEM ----
    for (int i = tid; i < HN * GCOLS; i += NTHR) {
        int k = i >> 5;
        int c = i & 31;            // c = lu*4 + g
        int lu = c >> 2, g = c & 3;
        int gc = g * HN + slice * UPC + lu;
        w_s[i]        = w_ih[(l * HN + k) * (4 * HN) + gc];
        w_s[4096 + i] = w_hh[(l * HN + k) * (4 * HN) + gc];
    }
    float bias[8];
#pragma unroll
    for (int c = 0; c < 8; c++) {
        int lu = cg * 2 + (c >> 2), g = c & 3;
        int gu = slice * UPC + lu;
        bias[c] = b_ih[l * 4 * HN + g * HN + gu] + b_hh[l * 4 * HN + g * HN + gu];
    }
    float cst[2] = {0.f, 0.f};     // cell state: 2 units for this (row, cg)
    __syncthreads();

    for (int t = 0; t < TN; t++) {
        // ---- combined dependency wait (each warp polls; loads hit same 64B line) ----
        if (l > 0 || t > 0) {
            const int* fA = (l > 0) ? &g_flag[l - 1][t][0] : &g_flag[l][t - 1][0];
            const int* fB = (t > 0) ? &g_flag[l][t - 1][0] : fA;
            const int* mine = (lane < 16) ? (fA + lane) : (fB + (lane - 16));
            while (!__all_sync(0xffffffffu, ld_acq(mine) != 0)) { }
        }

        // ---- stage tiles ----
        if (l > 0 && t > 0) {
            const float4* s1 = (const float4*)&g_hbuf[l - 1][t][0][0];
            const float4* s2 = (const float4*)&g_hbuf[l][t - 1][0][0];
            for (int i = tid; i < 2048; i += NTHR) {
                float4 v1 = __ldcg(s1 + i);
                float4 v2 = __ldcg(s2 + i);
                ((float4*)in_s)[i] = v1;
                ((float4*)hp_s)[i] = v2;
            }
        } else {
            if (l == 0) {
                // embedding gather, k-major write (lanes -> consecutive rows)
                int r  = tid & 63;
                int kh = (tid >> 6) << 5;    // 4 groups x 32 k each
                int tok = x[r * TN + t];
                const float* er = embed + tok * HN;
#pragma unroll
                for (int k = kh; k < kh + 32; k += 4) {
                    float4 v = *(const float4*)(er + k);
                    in_s[(k + 0) * BN + r] = v.x;
                    in_s[(k + 1) * BN + r] = v.y;
                    in_s[(k + 2) * BN + r] = v.z;
                    in_s[(k + 3) * BN + r] = v.w;
                }
            } else {
                const float4* s1 = (const float4*)&g_hbuf[l - 1][t][0][0];
                for (int i = tid; i < 2048; i += NTHR)
                    ((float4*)in_s)[i] = __ldcg(s1 + i);
            }
            if (t == 0) {
                for (int i = tid; i < 8192; i += NTHR) hp_s[i] = 0.f;
            } else {
                const float4* s2 = (const float4*)&g_hbuf[l][t - 1][0][0];
                for (int i = tid; i < 2048; i += NTHR)
                    ((float4*)hp_s)[i] = __ldcg(s2 + i);
            }
        }
        __syncthreads();

        // ---- gates: 1 row x 8 cols per thread ----
        float acc[8];
#pragma unroll
        for (int c = 0; c < 8; c++) acc[c] = bias[c];

        const float* wi = w_s + cg * 8;
        const float* wh = w_s + 4096 + cg * 8;
#pragma unroll 8
        for (int k = 0; k < HN; k++) {
            float a = in_s[k * BN + row];
            float p = hp_s[k * BN + row];
            float4 wiA = *(const float4*)(wi + k * GCOLS);
            float4 wiB = *(const float4*)(wi + k * GCOLS + 4);
            float4 whA = *(const float4*)(wh + k * GCOLS);
            float4 whB = *(const float4*)(wh + k * GCOLS + 4);
            acc[0] += a * wiA.x;  acc[0] += p * whA.x;
            acc[1] += a * wiA.y;  acc[1] += p * whA.y;
            acc[2] += a * wiA.z;  acc[2] += p * whA.z;
            acc[3] += a * wiA.w;  acc[3] += p * whA.w;
            acc[4] += a * wiB.x;  acc[4] += p * whB.x;
            acc[5] += a * wiB.y;  acc[5] += p * whB.y;
            acc[6] += a * wiB.z;  acc[6] += p * whB.z;
            acc[7] += a * wiB.w;  acc[7] += p * whB.w;
        }

        // ---- LSTM cell elementwise; publish h (lanes -> consecutive rows: coalesced) ----
#pragma unroll
        for (int uu = 0; uu < 2; uu++) {
            float iv = sig_(acc[uu * 4 + 0]);
            float fv = sig_(acc[uu * 4 + 1]);
            float gv = th_ (acc[uu * 4 + 2]);
            float ov = sig_(acc[uu * 4 + 3]);
            float c  = fv * cst[uu] + iv * gv;
            cst[uu] = c;
            float h = ov * th_(c);
            int gu = slice * UPC + cg * 2 + uu;
            g_hbuf[l][t][gu][row] = h;
            if (t == TN - 1) {
                int hidx = BN * TN * ON + (l * BN + row) * HN + gu;
                int cidx = hidx + LN * BN * HN;
                if (hidx < out_size) out[hidx] = h;
                if (cidx < out_size) out[cidx] = c;
            }
        }
        // Cumulative-release publish: barrier orders all threads' STGs before
        // tid0's gpu-scope release store (no per-thread MEMBAR needed).
        __syncthreads();
        if (tid == 0) st_rel(&g_flag[l][t][slice], 1);
    }
}

// outputs[b][t][o] = h7[t][b] . w_out[:,o] + b_out[o]; one CTA per t.
__global__ void __launch_bounds__(256, 1) proj_kernel(
    const float* __restrict__ w_out, const float* __restrict__ b_out,
    float* __restrict__ out, int out_size)
{
    extern __shared__ float sm[];
    float* h_s  = sm;          // [128][64]
    float* w_sm = sm + 8192;   // [128][65]
    int t = blockIdx.x;
    int tid = threadIdx.x;
    const float4* src = (const float4*)&g_hbuf[LN - 1][t][0][0];
    for (int i = tid; i < 2048; i += 256) ((float4*)h_s)[i] = src[i];
    for (int i = tid; i < HN * ON; i += 256) w_sm[i] = w_out[i];
    __syncthreads();
    for (int idx = tid; idx < BN * ON; idx += 256) {
        int b = idx / ON, o = idx - b * ON;
        float s = b_out[o];
#pragma unroll 16
        for (int k = 0; k < HN; k++)
            s += h_s[k * BN + b] * w_sm[k * ON + o];
        int oi = (b * TN + t) * ON + o;
        if (oi < out_size) out[oi] = s;
    }
}

extern "C" void kernel_launch(void* const* d_in, const int* in_sizes, int n_in,
                              void* d_out, int out_size)
{
    const int*   x     = (const int*)d_in[0];
    const float* embed = (const float*)d_in[1];
    const float* w_ih  = (const float*)d_in[2];
    const float* b_ih  = (const float*)d_in[3];
    const float* w_hh  = (const float*)d_in[4];
    const float* b_hh  = (const float*)d_in[5];
    const float* w_out = (const float*)d_in[6];
    const float* b_out = (const float*)d_in[7];
    float* out = (float*)d_out;

    cudaFuncSetAttribute(lstm_kernel, cudaFuncAttributeMaxDynamicSharedMemorySize, 98304);
    cudaFuncSetAttribute(proj_kernel, cudaFuncAttributeMaxDynamicSharedMemorySize, 66048);

    zero_flag_kernel<<<(LN * TN * CPL + 255) / 256, 256>>>();
    lstm_kernel<<<NCTA, NTHR, 98304>>>(x, embed, w_ih, b_ih, w_hh, b_hh, out, out_size);
    proj_kernel<<<TN, 256, 66048>>>(w_out, b_out, out, out_size);
}

// round 8
// speedup vs baseline: 2.3185x; 2.3185x over previous
#include <cuda_runtime.h>
#include <cstdint>

#define LN 8      // layers
#define BN 64     // batch
#define TN 512    // time steps
#define HN 128    // hidden
#define ON 65     // output vocab
#define CPL 16    // CTAs per layer
#define UPC 8     // hidden units per CTA
#define GCOLS 32  // gate columns per CTA
#define NTHR 128
#define NCTA (LN * CPL)

// Inter-layer activation buffer, k-major: h of layer l at time t, [HN][BN].
__device__ float g_hbuf[LN][TN][HN][BN];
// Per-slice completion flags (one 64B line per (l,t)).
__device__ int g_flag[LN][TN][CPL];

__device__ __forceinline__ float sig_(float x) {
    return __fdividef(1.f, 1.f + __expf(-x));
}
__device__ __forceinline__ float th_(float x) {
    return 1.f - __fdividef(2.f, __expf(2.f * x) + 1.f);
}
__device__ __forceinline__ int ld_acq(const int* p) {
    int v; asm volatile("ld.global.acquire.gpu.b32 %0, [%1];" : "=r"(v) : "l"(p) : "memory"); return v;
}
__device__ __forceinline__ void st_rel(int* p, int v) {
    asm volatile("st.global.release.gpu.b32 [%0], %1;" :: "l"(p), "r"(v) : "memory");
}
__device__ __forceinline__ void cpa16(uint32_t s, const void* g) {
    asm volatile("cp.async.cg.shared.global [%0], [%1], 16;" :: "r"(s), "l"(g));
}
__device__ __forceinline__ void cpa_drain() {
    asm volatile("cp.async.commit_group;" ::: "memory");
    asm volatile("cp.async.wait_group 0;" ::: "memory");
}
// Poll all 16 slice-flags of (l,t): lanes 0..15 each watch one flag (same 64B line).
__device__ __forceinline__ void wait_flags(const int* f, int lane) {
    for (;;) {
        int v = (lane < CPL) ? ld_acq(f + lane) : 1;
        if (__all_sync(0xffffffffu, v != 0)) break;
        __nanosleep(20);
    }
}

__global__ void __launch_bounds__(256, 1) zero_flag_kernel() {
    int i = blockIdx.x * blockDim.x + threadIdx.x;
    if (i < LN * TN * CPL) (&g_flag[0][0][0])[i] = 0;
}

__global__ void __launch_bounds__(NTHR, 1) lstm_kernel(
    const int* __restrict__ x, const float* __restrict__ embed,
    const float* __restrict__ w_ih, const float* __restrict__ b_ih,
    const float* __restrict__ w_hh, const float* __restrict__ b_hh,
    float* __restrict__ out, int out_size)
{
    extern __shared__ float sm[];
    float* w_s  = sm;          // [2][128][32]: w_ih then w_hh slice, layout [k][lu*4+g]
    float* in_s = sm + 8192;   // [128][64] k-major input tile
    float* hp_s = sm + 16384;  // [128][64] k-major h_prev tile

    const int cta   = blockIdx.x;
    const int l     = cta >> 4;
    const int slice = cta & 15;
    const int tid   = threadIdx.x;
    const int warp  = tid >> 5;    // 0..3 -> cols warp*8..+7 (units warp*2, warp*2+1)
    const int lane  = tid & 31;    // rows lane and lane+32

    const uint32_t in_sa = (uint32_t)__cvta_generic_to_shared(in_s);
    const uint32_t hp_sa = (uint32_t)__cvta_generic_to_shared(hp_s);

    // ---- one-time: weight slice into SMEM (stays for all 512 steps) ----
    for (int i = tid; i < HN * GCOLS; i += NTHR) {
        int k = i >> 5;
        int c = i & 31;            // c = lu*4 + g
        int lu = c >> 2, g = c & 3;
        int gc = g * HN + slice * UPC + lu;
        w_s[i]        = w_ih[(l * HN + k) * (4 * HN) + gc];
        w_s[4096 + i] = w_hh[(l * HN + k) * (4 * HN) + gc];
    }
    float bias[8];
#pragma unroll
    for (int c = 0; c < 8; c++) {
        int uu = c >> 2, g = c & 3;
        int gu = slice * UPC + warp * 2 + uu;
        bias[c] = b_ih[l * 4 * HN + g * HN + gu] + b_hh[l * 4 * HN + g * HN + gu];
    }
    float cst[2][2] = {{0.f, 0.f}, {0.f, 0.f}};   // cell state in registers
    __syncthreads();

    for (int t = 0; t < TN; t++) {
        // ---- stage h_prev (dep: own layer, t-1); issued first to overlap ----
        if (t > 0) {
            if (warp == 0) wait_flags(&g_flag[l][t - 1][0], lane);
            __syncthreads();
            const float4* s2 = (const float4*)&g_hbuf[l][t - 1][0][0];
#pragma unroll
            for (int j = 0; j < 16; j++) {
                int i = tid + j * NTHR;
                cpa16(hp_sa + i * 16, s2 + i);
            }
        } else {
            for (int i = tid; i < 8192; i += NTHR) hp_s[i] = 0.f;
        }

        // ---- stage input (dep: layer l-1, t) ----
        if (l > 0) {
            if (warp == 0) wait_flags(&g_flag[l - 1][t][0], lane);
            __syncthreads();
            const float4* s1 = (const float4*)&g_hbuf[l - 1][t][0][0];
#pragma unroll
            for (int j = 0; j < 16; j++) {
                int i = tid + j * NTHR;
                cpa16(in_sa + i * 16, s1 + i);
            }
        } else {
            // embedding gather, k-major write (lanes -> consecutive rows)
            int r  = tid & 63;
            int kh = (tid >> 6) << 6;
            int tok = x[r * TN + t];
            const float* er = embed + tok * HN;
#pragma unroll
            for (int k = kh; k < kh + 64; k += 4) {
                float4 v = *(const float4*)(er + k);
                in_s[(k + 0) * BN + r] = v.x;
                in_s[(k + 1) * BN + r] = v.y;
                in_s[(k + 2) * BN + r] = v.z;
                in_s[(k + 3) * BN + r] = v.w;
            }
        }
        cpa_drain();
        __syncthreads();

        // ---- gates = in @ Wih + hprev @ Whh + bias ----
        float acc[2][8];
#pragma unroll
        for (int c = 0; c < 8; c++) { acc[0][c] = bias[c]; acc[1][c] = bias[c]; }

        const float* wi = w_s + warp * 8;
        const float* wh = w_s + 4096 + warp * 8;
#pragma unroll 8
        for (int k = 0; k < HN; k++) {
            float a0 = in_s[k * BN + lane];
            float a1 = in_s[k * BN + lane + 32];
            float p0 = hp_s[k * BN + lane];
            float p1 = hp_s[k * BN + lane + 32];
            float4 wiA = *(const float4*)(wi + k * GCOLS);
            float4 wiB = *(const float4*)(wi + k * GCOLS + 4);
            float4 whA = *(const float4*)(wh + k * GCOLS);
            float4 whB = *(const float4*)(wh + k * GCOLS + 4);
            float wiv[8] = {wiA.x, wiA.y, wiA.z, wiA.w, wiB.x, wiB.y, wiB.z, wiB.w};
            float whv[8] = {whA.x, whA.y, whA.z, whA.w, whB.x, whB.y, whB.z, whB.w};
#pragma unroll
            for (int c = 0; c < 8; c++) {
                acc[0][c] += a0 * wiv[c];
                acc[0][c] += p0 * whv[c];
                acc[1][c] += a1 * wiv[c];
                acc[1][c] += p1 * whv[c];
            }
        }

        // ---- LSTM cell elementwise; publish h ----
#pragma unroll
        for (int rr = 0; rr < 2; rr++) {
            int r = lane + rr * 32;
#pragma unroll
            for (int uu = 0; uu < 2; uu++) {
                float iv = sig_(acc[rr][uu * 4 + 0]);
                float fv = sig_(acc[rr][uu * 4 + 1]);
                float gv = th_ (acc[rr][uu * 4 + 2]);
                float ov = sig_(acc[rr][uu * 4 + 3]);
                float c  = fv * cst[rr][uu] + iv * gv;
                cst[rr][uu] = c;
                float h = ov * th_(c);
                int gu = slice * UPC + warp * 2 + uu;
                g_hbuf[l][t][gu][r] = h;       // lanes -> consecutive r: coalesced
                if (t == TN - 1) {
                    int hidx = BN * TN * ON + (l * BN + r) * HN + gu;
                    int cidx = hidx + LN * BN * HN;
                    if (hidx < out_size) out[hidx] = h;
                    if (cidx < out_size) out[cidx] = c;
                }
            }
        }
        // Cumulative-release publish: bar.sync orders peers' STGs before tid0's
        // gpu-scope release store.
        __syncthreads();
        if (tid == 0) st_rel(&g_flag[l][t][slice], 1);
    }
}

// outputs[b][t][o] = h7[t][b] . w_out[:,o] + b_out[o]; one CTA per t.
__global__ void __launch_bounds__(256, 1) proj_kernel(
    const float* __restrict__ w_out, const float* __restrict__ b_out,
    float* __restrict__ out, int out_size)
{
    extern __shared__ float sm[];
    float* h_s  = sm;          // [128][64]
    float* w_sm = sm + 8192;   // [128][65]
    int t = blockIdx.x;
    int tid = threadIdx.x;
    const float4* src = (const float4*)&g_hbuf[LN - 1][t][0][0];
    for (int i = tid; i < 2048; i += 256) ((float4*)h_s)[i] = src[i];
    for (int i = tid; i < HN * ON; i += 256) w_sm[i] = w_out[i];
    __syncthreads();
    for (int idx = tid; idx < BN * ON; idx += 256) {
        int b = idx / ON, o = idx - b * ON;
        float s = b_out[o];
#pragma unroll 16
        for (int k = 0; k < HN; k++)
            s += h_s[k * BN + b] * w_sm[k * ON + o];
        int oi = (b * TN + t) * ON + o;
        if (oi < out_size) out[oi] = s;
    }
}

extern "C" void kernel_launch(void* const* d_in, const int* in_sizes, int n_in,
                              void* d_out, int out_size)
{
    const int*   x     = (const int*)d_in[0];
    const float* embed = (const float*)d_in[1];
    const float* w_ih  = (const float*)d_in[2];
    const float* b_ih  = (const float*)d_in[3];
    const float* w_hh  = (const float*)d_in[4];
    const float* b_hh  = (const float*)d_in[5];
    const float* w_out = (const float*)d_in[6];
    const float* b_out = (const float*)d_in[7];
    float* out = (float*)d_out;

    cudaFuncSetAttribute(lstm_kernel, cudaFuncAttributeMaxDynamicSharedMemorySize, 98304);
    cudaFuncSetAttribute(proj_kernel, cudaFuncAttributeMaxDynamicSharedMemorySize, 66048);

    zero_flag_kernel<<<(LN * TN * CPL + 255) / 256, 256>>>();
    lstm_kernel<<<NCTA, NTHR, 98304>>>(x, embed, w_ih, b_ih, w_hh, b_hh, out, out_size);
    proj_kernel<<<TN, 256, 66048>>>(w_out, b_out, out, out_size);
}